// round 15
// baseline (speedup 1.0000x reference)
#include <cuda_runtime.h>
#include <cuda_bf16.h>
#include <cstdint>

#define BB   512
#define CC   3
#define TT   500
#define DD   40
#define CD   120
#define NN   256
#define OUTN 12
#define BN   (BB*NN)        // 131072
#define B_J0 0.01f
#define BETA 1.8f
#define NCH  8

// ------------------------- device scratch (allocation-guard-safe) -----------
__device__ float         g_i1[(size_t)TT * BB * NN];   // 262 MB (i1, then i2in)
__device__ unsigned char g_lst[(size_t)TT * BB * 256]; // 65.5 MB s1 index lists
__device__ int           g_cnt[TT * BB];               // list lengths
__device__ float         g_W2inQ[4 * 256 * 64];        // [q][j][nl] quarters
__device__ float         g_W2recTp[NN * NN];           // [j][n]
__device__ __nv_bfloat16 g_W1hi[256 * 136];            // padded [n][136] bf16 hi
__device__ __nv_bfloat16 g_W1lo[256 * 136];            // padded [n][136] bf16 lo
__device__ float         g_acc[BB * OUTN];
// chunk-boundary state
__device__ float         g_k2m[BN], g_k2a[BN], g_k2s[BN];
__device__ float         g_k3m2[BN], g_k3a2[BN], g_k3s2[BN];
__device__ unsigned      g_k3w[BB * 8];
__device__ float         g_k3m3[BB * OUTN], g_k3ac[BB * OUTN];

// ------------------------- helpers ------------------------------------------
__device__ __forceinline__ unsigned smem_u32(const void* p) {
    return (unsigned)__cvta_generic_to_shared(p);
}
__device__ __forceinline__ void ldsm_x4(uint32_t& r0, uint32_t& r1,
                                        uint32_t& r2, uint32_t& r3, unsigned addr) {
    asm volatile("ldmatrix.sync.aligned.m8n8.x4.shared.b16 {%0,%1,%2,%3}, [%4];"
                 : "=r"(r0), "=r"(r1), "=r"(r2), "=r"(r3) : "r"(addr));
}
__device__ __forceinline__ void ldsm_x2(uint32_t& r0, uint32_t& r1, unsigned addr) {
    asm volatile("ldmatrix.sync.aligned.m8n8.x2.shared.b16 {%0,%1}, [%2];"
                 : "=r"(r0), "=r"(r1) : "r"(addr));
}
__device__ __forceinline__ void mma16816(float& c0, float& c1, float& c2, float& c3,
                                         uint32_t a0, uint32_t a1, uint32_t a2, uint32_t a3,
                                         uint32_t b0, uint32_t b1) {
    asm volatile("mma.sync.aligned.m16n8k16.row.col.f32.bf16.bf16.f32 "
                 "{%0,%1,%2,%3}, {%4,%5,%6,%7}, {%8,%9}, {%0,%1,%2,%3};"
                 : "+f"(c0), "+f"(c1), "+f"(c2), "+f"(c3)
                 : "r"(a0), "r"(a1), "r"(a2), "r"(a3), "r"(b0), "r"(b1));
}

// ------------------------- K0: weight layout prep ---------------------------
__global__ void k0_prep(const float* __restrict__ W2_in,
                        const float* __restrict__ W2_rec,
                        const float* __restrict__ W1)
{
    int j = blockIdx.x;
    int n = threadIdx.x;
    g_W2recTp[j * NN + n] = W2_rec[n * NN + j];
    g_W2inQ[(((n >> 6) * 256) + j) * 64 + (n & 63)] = W2_in[n * NN + j];
    if (n < 136) {
        float f = (n < CD) ? W1[j * CD + n] : 0.0f;
        __nv_bfloat16 hb = __float2bfloat16(f);
        __nv_bfloat16 lb = __float2bfloat16(f - __bfloat162float(hb));
        g_W1hi[j * 136 + n] = hb;
        g_W1lo[j * 136 + n] = lb;
    }
}

// ------------------------- K1: spikify + i1 GEMM via tensor cores -----------
#define K1_LDK 136
#define K1_SMEM (64*K1_LDK*2 + 2*256*K1_LDK*2)   // 156672
__global__ void __launch_bounds__(512, 1)
k1_gemm1(const float* __restrict__ x, const float* __restrict__ thrp,
         const float* __restrict__ b1, int t0)
{
    extern __shared__ char smraw[];
    __nv_bfloat16* xs  = (__nv_bfloat16*)smraw;                        // [64][136]
    __nv_bfloat16* whi = (__nv_bfloat16*)(smraw + 64*K1_LDK*2);        // [256][136]
    __nv_bfloat16* wlo = (__nv_bfloat16*)(smraw + 64*K1_LDK*2 + 256*K1_LDK*2);

    const int tid = threadIdx.x;
    const int p0  = blockIdx.x * 64 + t0 * BB;
    const int t   = p0 >> 9;
    const int b0  = p0 & 511;
    const float thr = *thrp;

    for (int i = tid; i < 4352; i += 512) {
        ((float4*)whi)[i] = ((const float4*)g_W1hi)[i];
        ((float4*)wlo)[i] = ((const float4*)g_W1lo)[i];
    }
    {
        const __nv_bfloat16 z = __float2bfloat16(0.0f);
        for (int i = tid; i < 64 * 8; i += 512) {
            int r = i >> 3, k = 120 + (i & 7);
            xs[r * K1_LDK + k] = z;
        }
    }
    for (int i = tid; i < 64 * CD; i += 512) {
        int r  = i / CD;
        int cd = i % CD;
        int c  = cd / DD, d = cd % DD;
        float xv = x[(((size_t)(b0 + r) * CC + c) * TT + t) * DD + d];
        float s  = (xv > thr) ? 1.0f : ((xv < -thr) ? -1.0f : 0.0f);
        xs[r * K1_LDK + cd] = __float2bfloat16(s);
    }
    __syncthreads();

    const int warp = tid >> 5, lane = tid & 31;
    const int mb = (warp & 3) * 16;
    const int nb = (warp >> 2) * 64;

    float acc[8][4];
    #pragma unroll
    for (int j = 0; j < 8; j++)
        #pragma unroll
        for (int u = 0; u < 4; u++) acc[j][u] = 0.0f;

    const unsigned a_base  = smem_u32(xs)  + (unsigned)(mb + (lane & 15)) * (K1_LDK * 2)
                                           + ((lane >> 4) << 4);
    const unsigned bkoff   = ((lane >> 3) & 1) << 4;
    const unsigned bh_base = smem_u32(whi) + (unsigned)(nb + (lane & 7)) * (K1_LDK * 2) + bkoff;
    const unsigned bl_base = smem_u32(wlo) + (unsigned)(nb + (lane & 7)) * (K1_LDK * 2) + bkoff;

    #pragma unroll
    for (int kt = 0; kt < 8; kt++) {
        uint32_t a0, a1, a2, a3;
        ldsm_x4(a0, a1, a2, a3, a_base + kt * 32);
        #pragma unroll
        for (int j = 0; j < 8; j++) {
            uint32_t br0, br1;
            ldsm_x2(br0, br1, bh_base + (unsigned)j * (8 * K1_LDK * 2) + kt * 32);
            mma16816(acc[j][0], acc[j][1], acc[j][2], acc[j][3],
                     a0, a1, a2, a3, br0, br1);
            ldsm_x2(br0, br1, bl_base + (unsigned)j * (8 * K1_LDK * 2) + kt * 32);
            mma16816(acc[j][0], acc[j][1], acc[j][2], acc[j][3],
                     a0, a1, a2, a3, br0, br1);
        }
    }

    const int g  = lane >> 2, tg = lane & 3;
    const int r0 = mb + g, r1 = r0 + 8;
    #pragma unroll
    for (int j = 0; j < 8; j++) {
        int n = nb + j * 8 + tg * 2;
        float2 bv = *(const float2*)&b1[n];
        size_t base0 = (size_t)t * BN + (size_t)(b0 + r0) * NN + n;
        size_t base1 = (size_t)t * BN + (size_t)(b0 + r1) * NN + n;
        *(float2*)&g_i1[base0] = make_float2(acc[j][0] + bv.x, acc[j][1] + bv.y);
        *(float2*)&g_i1[base1] = make_float2(acc[j][2] + bv.x, acc[j][3] + bv.y);
    }
}

// ------------------------- K2: layer-1 ALIF scan chunk ----------------------
__global__ void __launch_bounds__(256)
k2_scan1(const float* __restrict__ tau_adp1, const float* __restrict__ tau_m1,
         int t0, int t1)
{
    __shared__ unsigned swords[2][4][8];

    const int b    = blockIdx.x;
    const int tid  = threadIdx.x;
    const int n    = tid;
    const int lane = tid & 31;
    const int wid  = tid >> 5;
    const unsigned ltm = (1u << lane) - 1u;
    const int gid  = b * NN + n;

    const float alpha = __expf(-1.0f / tau_m1[n]);
    const float rho   = __expf(-1.0f / tau_adp1[n]);
    const float ca = 1.0f - alpha, cr = 1.0f - rho;

    float m, a, s;
    if (t0 == 0) { m = 0.f; a = B_J0; s = 0.f; }
    else { m = g_k2m[gid]; a = g_k2a[gid]; s = g_k2s[gid]; }

    const float* ip = g_i1 + gid;

    for (int t4 = t0; t4 < t1; t4 += 4) {
        const int buf = (t4 >> 2) & 1;
        float iv[4];
        #pragma unroll
        for (int k = 0; k < 4; k++) iv[k] = ip[(size_t)(t4 + k) * BN];
        #pragma unroll
        for (int k = 0; k < 4; k++) {
            a = rho * a + cr * s;
            float Bth = B_J0 + BETA * a;
            m = alpha * m + ca * iv[k] - Bth * s;
            s = (m - Bth > 0.f) ? 1.f : 0.f;
            unsigned bal = __ballot_sync(0xffffffffu, s > 0.5f);
            if (lane == 0) swords[buf][k][wid] = bal;
        }
        __syncthreads();
        #pragma unroll
        for (int k = 0; k < 4; k++) {
            const int t = t4 + k;
            unsigned wv[8];
            #pragma unroll
            for (int w = 0; w < 8; w++) wv[w] = swords[buf][k][w];
            int off = 0, myoff = 0;
            #pragma unroll
            for (int w = 0; w < 8; w++) {
                if (w == wid) myoff = off;
                off += __popc(wv[w]);
            }
            unsigned wd = wv[wid];
            if ((wd >> lane) & 1u)
                g_lst[(size_t)(t * BB + b) * 256 + myoff + __popc(wd & ltm)] =
                    (unsigned char)(wid * 32 + lane);
            if (tid == 0) g_cnt[t * BB + b] = off;
        }
    }
    if (t1 != TT) { g_k2m[gid] = m; g_k2a[gid] = a; g_k2s[gid] = s; }
}

// ------------------------- K2.5: i2in chunk (proven R5 core) ----------------
#define K25_SMEM (64*1024 + 8*2*64*4)
__global__ void __launch_bounds__(256, 2)
k25_gemm2in(const float* __restrict__ b2_in, const float* __restrict__ b2_rec,
            int t0)
{
    extern __shared__ float sm[];
    float2*   w2  = (float2*)sm;                  // [j*32+lane] pairs
    unsigned* lsb = (unsigned*)(sm + 16384);      // [8 warps][2][64]

    const int idx  = blockIdx.x;
    const int q    = idx & 3;
    const int bh   = (idx >> 2) & 1;
    const int t    = (idx >> 3) + t0;
    const int tid  = threadIdx.x;
    const int lane = tid & 31;
    const int wid  = tid >> 5;

    {
        const float4* src = (const float4*)(g_W2inQ + q * 256 * 64);
        float4* dst = (float4*)sm;
        for (int i = tid; i < 4096; i += 256) dst[i] = src[i];
    }
    const int n0 = q * 64 + lane * 2;
    const float2 bias2 = make_float2(b2_in[n0] + b2_rec[n0],
                                     b2_in[n0 + 1] + b2_rec[n0 + 1]);
    __syncthreads();

    const int bbase = bh * 256 + wid * 32;
    const int cb    = t * BB + bbase;
    const int mycnt = g_cnt[cb + lane];
    unsigned* mybuf = lsb + wid * 128;

    {
        int c0  = __shfl_sync(0xffffffffu, mycnt, 0);
        int nch = (c0 + 15) >> 4;
        if (lane < nch) {
            uint4 v = ((const uint4*)(g_lst + (size_t)cb * 256))[lane];
            unsigned* d = mybuf + lane * 4;
            d[0] = v.x; d[1] = v.y; d[2] = v.z; d[3] = v.w;
        }
        __syncwarp();
    }

    for (int i = 0; i < 32; i++) {
        uint4 vn = make_uint4(0, 0, 0, 0);
        int nchn = 0;
        if (i + 1 < 32) {
            int cn = __shfl_sync(0xffffffffu, mycnt, i + 1);
            nchn = (cn + 15) >> 4;
            if (lane < nchn)
                vn = ((const uint4*)(g_lst + (size_t)(cb + i + 1) * 256))[lane];
        }
        const int cnt = __shfl_sync(0xffffffffu, mycnt, i);
        const unsigned* lb = mybuf + (i & 1) * 64;

        float2 acc = bias2;
        int k = 0;
        for (; k + 4 <= cnt; k += 4) {
            unsigned w = lb[k >> 2];
            int j0 = w & 255, j1 = (w >> 8) & 255, j2 = (w >> 16) & 255, j3 = w >> 24;
            float2 v0 = w2[j0 * 32 + lane];
            float2 v1 = w2[j1 * 32 + lane];
            float2 v2 = w2[j2 * 32 + lane];
            float2 v3 = w2[j3 * 32 + lane];
            acc.x += v0.x; acc.y += v0.y;
            acc.x += v1.x; acc.y += v1.y;
            acc.x += v2.x; acc.y += v2.y;
            acc.x += v3.x; acc.y += v3.y;
        }
        if (k < cnt) {
            unsigned w = lb[k >> 2];
            for (; k < cnt; k++) {
                int j = (w >> (8 * (k & 3))) & 255;
                float2 v = w2[j * 32 + lane];
                acc.x += v.x; acc.y += v.y;
            }
        }

        ((float2*)(g_i1 + (size_t)t * BN + (size_t)(bbase + i) * NN + q * 64))[lane] = acc;

        if (i + 1 < 32 && lane < nchn) {
            unsigned* d = mybuf + ((i + 1) & 1) * 64 + lane * 4;
            d[0] = vn.x; d[1] = vn.y; d[2] = vn.z; d[3] = vn.w;
        }
        __syncwarp();
    }
}

// ------------------------- K3: recurrent chunk (R10 core + state spill) -----
__global__ void __launch_bounds__(256)
k3_recurrent(const float* __restrict__ W3, const float* __restrict__ b3,
             const float* __restrict__ tau_adp2, const float* __restrict__ tau_m2,
             const float* __restrict__ tau_m3, int t0, int t1)
{
    __shared__ float    W3s[OUTN * 257];
    __shared__ unsigned words[8];
    __shared__ int      lst2[256];

    const int b    = blockIdx.x;
    const int tid  = threadIdx.x;
    const int n    = tid;
    const int lane = tid & 31;
    const int wid  = tid >> 5;
    const unsigned ltm = (1u << lane) - 1u;
    const int gid  = b * NN + n;
    const bool first = (t0 == 0), last = (t1 == TT);

    for (int i = tid; i < OUTN * NN; i += 256)
        W3s[(i >> 8) * 257 + (i & 255)] = W3[i];
    if (tid < 8) words[tid] = first ? 0u : g_k3w[b * 8 + tid];

    const float al = __expf(-1.0f / tau_m2[n]);
    const float rh = __expf(-1.0f / tau_adp2[n]);
    float m2, a2, s2;
    if (first) { m2 = 0.f; a2 = B_J0; s2 = 0.f; }
    else { m2 = g_k3m2[gid]; a2 = g_k3a2[gid]; s2 = g_k3s2[gid]; }

    float al3 = 1.f, m3 = 0.f, accr = 0.f, b3v = 0.f;
    if (tid < OUTN) {
        al3 = __expf(-1.0f / tau_m3[tid]);
        b3v = b3[tid];
        if (!first) { m3 = g_k3m3[b * OUTN + tid]; accr = g_k3ac[b * OUTN + tid]; }
    }

    const float* __restrict__ w2rf = g_W2recTp;
    const float* __restrict__ i2p  = g_i1 + gid;

    __syncthreads();

    float iv = i2p[(size_t)t0 * BN];

    for (int t = t0; t < t1; t++) {
        __syncthreads();   // prev ballots visible; lst2 free

        const int tn = (t + 1 < t1) ? (t + 1) : t;
        float nv = i2p[(size_t)tn * BN];

        if (tid < OUTN && t > 0) {
            float i3 = b3v;
            const float* wr = &W3s[tid * 257];
            #pragma unroll
            for (int w = 0; w < 8; w++) {
                unsigned mm = words[w];
                int base = w * 32;
                while (mm) {
                    int j = __ffs((int)mm) - 1;
                    mm &= mm - 1;
                    i3 += wr[base + j];
                }
            }
            m3 = al3 * m3 + (1.0f - al3) * i3;
            accr += m3;
        }

        unsigned wv[8];
        #pragma unroll
        for (int w = 0; w < 8; w++) wv[w] = words[w];
        int off = 0, myoff = 0;
        #pragma unroll
        for (int w = 0; w < 8; w++) {
            if (w == wid) myoff = off;
            off += __popc(wv[w]);
        }
        const int cnt2 = off;
        unsigned wd = wv[wid];
        if ((wd >> lane) & 1u)
            lst2[myoff + __popc(wd & ltm)] = wid * 32 + lane;
        __syncthreads();

        float i2 = iv;
        {
            int k = 0;
            for (; k + 8 <= cnt2; k += 8) {
                int j0 = lst2[k],     j1 = lst2[k + 1], j2 = lst2[k + 2], j3 = lst2[k + 3];
                int j4 = lst2[k + 4], j5 = lst2[k + 5], j6 = lst2[k + 6], j7 = lst2[k + 7];
                float v0 = w2rf[j0 * NN + n];
                float v1 = w2rf[j1 * NN + n];
                float v2 = w2rf[j2 * NN + n];
                float v3 = w2rf[j3 * NN + n];
                float v4 = w2rf[j4 * NN + n];
                float v5 = w2rf[j5 * NN + n];
                float v6 = w2rf[j6 * NN + n];
                float v7 = w2rf[j7 * NN + n];
                i2 += v0; i2 += v1; i2 += v2; i2 += v3;
                i2 += v4; i2 += v5; i2 += v6; i2 += v7;
            }
            for (; k < cnt2; k++) i2 += w2rf[lst2[k] * NN + n];
        }

        a2 = rh * a2 + (1.0f - rh) * s2;
        float Bth = B_J0 + BETA * a2;
        m2 = al * m2 + (1.0f - al) * i2 - Bth * s2;
        s2 = (m2 - Bth > 0.f) ? 1.f : 0.f;

        unsigned bal = __ballot_sync(0xffffffffu, s2 > 0.5f);
        if (lane == 0) words[wid] = bal;
        iv = nv;
    }

    __syncthreads();
    if (last) {
        if (tid < OUTN) {
            float i3 = b3v;
            const float* wr = &W3s[tid * 257];
            #pragma unroll
            for (int w = 0; w < 8; w++) {
                unsigned mm = words[w];
                int base = w * 32;
                while (mm) {
                    int j = __ffs((int)mm) - 1;
                    mm &= mm - 1;
                    i3 += wr[base + j];
                }
            }
            m3 = al3 * m3 + (1.0f - al3) * i3;
            accr += m3;
            g_acc[b * OUTN + tid] = accr;
        }
    } else {
        g_k3m2[gid] = m2; g_k3a2[gid] = a2; g_k3s2[gid] = s2;
        if (tid < 8) g_k3w[b * 8 + tid] = words[tid];
        if (tid < OUTN) { g_k3m3[b * OUTN + tid] = m3; g_k3ac[b * OUTN + tid] = accr; }
    }
}

// ------------------------- K4: log-softmax ----------------------------------
__global__ void __launch_bounds__(256)
k4_softmax(float* __restrict__ out)
{
    int b = blockIdx.x * 256 + threadIdx.x;
    if (b >= BB) return;
    float v[OUTN];
    float mx = -1e30f;
    #pragma unroll
    for (int o = 0; o < OUTN; o++) {
        v[o] = g_acc[b * OUTN + o] * (1.0f / (float)TT);
        mx = fmaxf(mx, v[o]);
    }
    float sum = 0.f;
    #pragma unroll
    for (int o = 0; o < OUTN; o++) sum += __expf(v[o] - mx);
    float lse = mx + __logf(sum);
    #pragma unroll
    for (int o = 0; o < OUTN; o++) out[b * OUTN + o] = v[o] - lse;
}

// ------------------------- launch: priority-pipelined chunks ----------------
static const int CH[NCH + 1] = {0, 64, 128, 192, 256, 320, 384, 448, 500};

extern "C" void kernel_launch(void* const* d_in, const int* in_sizes, int n_in,
                              void* d_out, int out_size)
{
    const float* x        = (const float*)d_in[0];
    const float* thr      = (const float*)d_in[1];
    const float* W1       = (const float*)d_in[2];
    const float* b1       = (const float*)d_in[3];
    const float* W2_in    = (const float*)d_in[4];
    const float* b2_in    = (const float*)d_in[5];
    const float* W2_rec   = (const float*)d_in[6];
    const float* b2_rec   = (const float*)d_in[7];
    const float* W3       = (const float*)d_in[8];
    const float* b3       = (const float*)d_in[9];
    const float* tau_adp1 = (const float*)d_in[10];
    const float* tau_m1   = (const float*)d_in[11];
    const float* tau_adp2 = (const float*)d_in[12];
    const float* tau_m2   = (const float*)d_in[13];
    const float* tau_m3   = (const float*)d_in[14];
    float* out = (float*)d_out;

    static cudaStream_t sB = nullptr;
    static cudaEvent_t  evFork, evP[NCH], evJoin;
    if (sB == nullptr) {
        int loPri = 0, hiPri = 0;
        cudaDeviceGetStreamPriorityRange(&loPri, &hiPri);
        cudaStreamCreateWithPriority(&sB, cudaStreamNonBlocking, hiPri);
        cudaEventCreateWithFlags(&evFork, cudaEventDisableTiming);
        for (int c = 0; c < NCH; c++)
            cudaEventCreateWithFlags(&evP[c], cudaEventDisableTiming);
        cudaEventCreateWithFlags(&evJoin, cudaEventDisableTiming);
    }

    cudaFuncSetAttribute(k1_gemm1,    cudaFuncAttributeMaxDynamicSharedMemorySize, K1_SMEM);
    cudaFuncSetAttribute(k25_gemm2in, cudaFuncAttributeMaxDynamicSharedMemorySize, K25_SMEM);

    // prologue pipeline on the capture stream (low priority)
    k0_prep<<<NN, NN>>>(W2_in, W2_rec, W1);
    cudaEventRecord(evFork, 0);
    cudaStreamWaitEvent(sB, evFork, 0);

    for (int c = 0; c < NCH; c++) {
        const int t0 = CH[c], t1 = CH[c + 1], len = t1 - t0;
        k1_gemm1<<<len * 8, 512, K1_SMEM>>>(x, thr, b1, t0);
        k2_scan1<<<BB, 256>>>(tau_adp1, tau_m1, t0, t1);
        k25_gemm2in<<<len * 8, 256, K25_SMEM>>>(b2_in, b2_rec, t0);
        cudaEventRecord(evP[c], 0);
    }

    // recurrent core on the high-priority stream, gated per chunk
    for (int c = 0; c < NCH; c++) {
        cudaStreamWaitEvent(sB, evP[c], 0);
        k3_recurrent<<<BB, 256, 0, sB>>>(W3, b3, tau_adp2, tau_m2, tau_m3,
                                         CH[c], CH[c + 1]);
    }
    cudaEventRecord(evJoin, sB);
    cudaStreamWaitEvent(0, evJoin, 0);

    k4_softmax<<<(BB + 255) / 256, 256>>>(out);
}

// round 16
// speedup vs baseline: 1.0356x; 1.0356x over previous
#include <cuda_runtime.h>
#include <cuda_bf16.h>
#include <cstdint>

#define BB   512
#define CC   3
#define TT   500
#define DD   40
#define CD   120
#define NN   256
#define OUTN 12
#define BN   (BB*NN)        // 131072
#define B_J0 0.01f
#define BETA 1.8f
#define NCH  4

// ------------------------- device scratch (allocation-guard-safe) -----------
__device__ float         g_i1[(size_t)TT * BB * NN];   // 262 MB (i1, then i2in)
__device__ unsigned char g_lst[(size_t)TT * BB * 256]; // 65.5 MB s1 index lists
__device__ int           g_cnt[TT * BB];               // list lengths
__device__ float         g_W2inQ[4 * 256 * 64];        // [q][j][nl] quarters
__device__ float         g_W2recTp[NN * NN];           // [j][n]
__device__ __nv_bfloat16 g_W1hi[256 * 136];            // padded [n][136] bf16 hi
__device__ __nv_bfloat16 g_W1lo[256 * 136];            // padded [n][136] bf16 lo
__device__ float         g_acc[BB * OUTN];
// chunk-boundary state
__device__ float         g_k2m[BN], g_k2a[BN], g_k2s[BN];
__device__ float         g_k3m2[BN], g_k3a2[BN], g_k3s2[BN];
__device__ unsigned      g_k3w[BB * 8];
__device__ float         g_k3m3[BB * OUTN], g_k3ac[BB * OUTN];

// ------------------------- helpers ------------------------------------------
__device__ __forceinline__ unsigned smem_u32(const void* p) {
    return (unsigned)__cvta_generic_to_shared(p);
}
__device__ __forceinline__ void ldsm_x4(uint32_t& r0, uint32_t& r1,
                                        uint32_t& r2, uint32_t& r3, unsigned addr) {
    asm volatile("ldmatrix.sync.aligned.m8n8.x4.shared.b16 {%0,%1,%2,%3}, [%4];"
                 : "=r"(r0), "=r"(r1), "=r"(r2), "=r"(r3) : "r"(addr));
}
__device__ __forceinline__ void ldsm_x2(uint32_t& r0, uint32_t& r1, unsigned addr) {
    asm volatile("ldmatrix.sync.aligned.m8n8.x2.shared.b16 {%0,%1}, [%2];"
                 : "=r"(r0), "=r"(r1) : "r"(addr));
}
__device__ __forceinline__ void mma16816(float& c0, float& c1, float& c2, float& c3,
                                         uint32_t a0, uint32_t a1, uint32_t a2, uint32_t a3,
                                         uint32_t b0, uint32_t b1) {
    asm volatile("mma.sync.aligned.m16n8k16.row.col.f32.bf16.bf16.f32 "
                 "{%0,%1,%2,%3}, {%4,%5,%6,%7}, {%8,%9}, {%0,%1,%2,%3};"
                 : "+f"(c0), "+f"(c1), "+f"(c2), "+f"(c3)
                 : "r"(a0), "r"(a1), "r"(a2), "r"(a3), "r"(b0), "r"(b1));
}

// ------------------------- K0: weight layout prep ---------------------------
__global__ void k0_prep(const float* __restrict__ W2_in,
                        const float* __restrict__ W2_rec,
                        const float* __restrict__ W1)
{
    int j = blockIdx.x;
    int n = threadIdx.x;
    g_W2recTp[j * NN + n] = W2_rec[n * NN + j];
    g_W2inQ[(((n >> 6) * 256) + j) * 64 + (n & 63)] = W2_in[n * NN + j];
    if (n < 136) {
        float f = (n < CD) ? W1[j * CD + n] : 0.0f;
        __nv_bfloat16 hb = __float2bfloat16(f);
        __nv_bfloat16 lb = __float2bfloat16(f - __bfloat162float(hb));
        g_W1hi[j * 136 + n] = hb;
        g_W1lo[j * 136 + n] = lb;
    }
}

// ------------------------- K1: spikify + i1 GEMM via tensor cores -----------
#define K1_LDK 136
#define K1_SMEM (64*K1_LDK*2 + 2*256*K1_LDK*2)   // 156672
__global__ void __launch_bounds__(512, 1)
k1_gemm1(const float* __restrict__ x, const float* __restrict__ thrp,
         const float* __restrict__ b1, int t0)
{
    extern __shared__ char smraw[];
    __nv_bfloat16* xs  = (__nv_bfloat16*)smraw;                        // [64][136]
    __nv_bfloat16* whi = (__nv_bfloat16*)(smraw + 64*K1_LDK*2);        // [256][136]
    __nv_bfloat16* wlo = (__nv_bfloat16*)(smraw + 64*K1_LDK*2 + 256*K1_LDK*2);

    const int tid = threadIdx.x;
    const int p0  = blockIdx.x * 64 + t0 * BB;
    const int t   = p0 >> 9;
    const int b0  = p0 & 511;
    const float thr = *thrp;

    for (int i = tid; i < 4352; i += 512) {
        ((float4*)whi)[i] = ((const float4*)g_W1hi)[i];
        ((float4*)wlo)[i] = ((const float4*)g_W1lo)[i];
    }
    {
        const __nv_bfloat16 z = __float2bfloat16(0.0f);
        for (int i = tid; i < 64 * 8; i += 512) {
            int r = i >> 3, k = 120 + (i & 7);
            xs[r * K1_LDK + k] = z;
        }
    }
    for (int i = tid; i < 64 * CD; i += 512) {
        int r  = i / CD;
        int cd = i % CD;
        int c  = cd / DD, d = cd % DD;
        float xv = x[(((size_t)(b0 + r) * CC + c) * TT + t) * DD + d];
        float s  = (xv > thr) ? 1.0f : ((xv < -thr) ? -1.0f : 0.0f);
        xs[r * K1_LDK + cd] = __float2bfloat16(s);
    }
    __syncthreads();

    const int warp = tid >> 5, lane = tid & 31;
    const int mb = (warp & 3) * 16;
    const int nb = (warp >> 2) * 64;

    float acc[8][4];
    #pragma unroll
    for (int j = 0; j < 8; j++)
        #pragma unroll
        for (int u = 0; u < 4; u++) acc[j][u] = 0.0f;

    const unsigned a_base  = smem_u32(xs)  + (unsigned)(mb + (lane & 15)) * (K1_LDK * 2)
                                           + ((lane >> 4) << 4);
    const unsigned bkoff   = ((lane >> 3) & 1) << 4;
    const unsigned bh_base = smem_u32(whi) + (unsigned)(nb + (lane & 7)) * (K1_LDK * 2) + bkoff;
    const unsigned bl_base = smem_u32(wlo) + (unsigned)(nb + (lane & 7)) * (K1_LDK * 2) + bkoff;

    #pragma unroll
    for (int kt = 0; kt < 8; kt++) {
        uint32_t a0, a1, a2, a3;
        ldsm_x4(a0, a1, a2, a3, a_base + kt * 32);
        #pragma unroll
        for (int j = 0; j < 8; j++) {
            uint32_t br0, br1;
            ldsm_x2(br0, br1, bh_base + (unsigned)j * (8 * K1_LDK * 2) + kt * 32);
            mma16816(acc[j][0], acc[j][1], acc[j][2], acc[j][3],
                     a0, a1, a2, a3, br0, br1);
            ldsm_x2(br0, br1, bl_base + (unsigned)j * (8 * K1_LDK * 2) + kt * 32);
            mma16816(acc[j][0], acc[j][1], acc[j][2], acc[j][3],
                     a0, a1, a2, a3, br0, br1);
        }
    }

    const int g  = lane >> 2, tg = lane & 3;
    const int r0 = mb + g, r1 = r0 + 8;
    #pragma unroll
    for (int j = 0; j < 8; j++) {
        int n = nb + j * 8 + tg * 2;
        float2 bv = *(const float2*)&b1[n];
        size_t base0 = (size_t)t * BN + (size_t)(b0 + r0) * NN + n;
        size_t base1 = (size_t)t * BN + (size_t)(b0 + r1) * NN + n;
        *(float2*)&g_i1[base0] = make_float2(acc[j][0] + bv.x, acc[j][1] + bv.y);
        *(float2*)&g_i1[base1] = make_float2(acc[j][2] + bv.x, acc[j][3] + bv.y);
    }
}

// ------------------------- K2: layer-1 ALIF scan chunk ----------------------
__global__ void __launch_bounds__(256)
k2_scan1(const float* __restrict__ tau_adp1, const float* __restrict__ tau_m1,
         int t0, int t1)
{
    __shared__ unsigned swords[2][4][8];

    const int b    = blockIdx.x;
    const int tid  = threadIdx.x;
    const int n    = tid;
    const int lane = tid & 31;
    const int wid  = tid >> 5;
    const unsigned ltm = (1u << lane) - 1u;
    const int gid  = b * NN + n;

    const float alpha = __expf(-1.0f / tau_m1[n]);
    const float rho   = __expf(-1.0f / tau_adp1[n]);
    const float ca = 1.0f - alpha, cr = 1.0f - rho;

    float m, a, s;
    if (t0 == 0) { m = 0.f; a = B_J0; s = 0.f; }
    else { m = g_k2m[gid]; a = g_k2a[gid]; s = g_k2s[gid]; }

    const float* ip = g_i1 + gid;

    for (int t4 = t0; t4 < t1; t4 += 4) {
        const int buf = (t4 >> 2) & 1;
        float iv[4];
        #pragma unroll
        for (int k = 0; k < 4; k++) iv[k] = ip[(size_t)(t4 + k) * BN];
        #pragma unroll
        for (int k = 0; k < 4; k++) {
            a = rho * a + cr * s;
            float Bth = B_J0 + BETA * a;
            m = alpha * m + ca * iv[k] - Bth * s;
            s = (m - Bth > 0.f) ? 1.f : 0.f;
            unsigned bal = __ballot_sync(0xffffffffu, s > 0.5f);
            if (lane == 0) swords[buf][k][wid] = bal;
        }
        __syncthreads();
        #pragma unroll
        for (int k = 0; k < 4; k++) {
            const int t = t4 + k;
            unsigned wv[8];
            #pragma unroll
            for (int w = 0; w < 8; w++) wv[w] = swords[buf][k][w];
            int off = 0, myoff = 0;
            #pragma unroll
            for (int w = 0; w < 8; w++) {
                if (w == wid) myoff = off;
                off += __popc(wv[w]);
            }
            unsigned wd = wv[wid];
            if ((wd >> lane) & 1u)
                g_lst[(size_t)(t * BB + b) * 256 + myoff + __popc(wd & ltm)] =
                    (unsigned char)(wid * 32 + lane);
            if (tid == 0) g_cnt[t * BB + b] = off;
        }
    }
    if (t1 != TT) { g_k2m[gid] = m; g_k2a[gid] = a; g_k2s[gid] = s; }
}

// ------------------------- K2.5: i2in chunk (proven R5 core) ----------------
#define K25_SMEM (64*1024 + 8*2*64*4)
__global__ void __launch_bounds__(256, 2)
k25_gemm2in(const float* __restrict__ b2_in, const float* __restrict__ b2_rec,
            int t0)
{
    extern __shared__ float sm[];
    float2*   w2  = (float2*)sm;                  // [j*32+lane] pairs
    unsigned* lsb = (unsigned*)(sm + 16384);      // [8 warps][2][64]

    const int idx  = blockIdx.x;
    const int q    = idx & 3;
    const int bh   = (idx >> 2) & 1;
    const int t    = (idx >> 3) + t0;
    const int tid  = threadIdx.x;
    const int lane = tid & 31;
    const int wid  = tid >> 5;

    {
        const float4* src = (const float4*)(g_W2inQ + q * 256 * 64);
        float4* dst = (float4*)sm;
        for (int i = tid; i < 4096; i += 256) dst[i] = src[i];
    }
    const int n0 = q * 64 + lane * 2;
    const float2 bias2 = make_float2(b2_in[n0] + b2_rec[n0],
                                     b2_in[n0 + 1] + b2_rec[n0 + 1]);
    __syncthreads();

    const int bbase = bh * 256 + wid * 32;
    const int cb    = t * BB + bbase;
    const int mycnt = g_cnt[cb + lane];
    unsigned* mybuf = lsb + wid * 128;

    {
        int c0  = __shfl_sync(0xffffffffu, mycnt, 0);
        int nch = (c0 + 15) >> 4;
        if (lane < nch) {
            uint4 v = ((const uint4*)(g_lst + (size_t)cb * 256))[lane];
            unsigned* d = mybuf + lane * 4;
            d[0] = v.x; d[1] = v.y; d[2] = v.z; d[3] = v.w;
        }
        __syncwarp();
    }

    for (int i = 0; i < 32; i++) {
        uint4 vn = make_uint4(0, 0, 0, 0);
        int nchn = 0;
        if (i + 1 < 32) {
            int cn = __shfl_sync(0xffffffffu, mycnt, i + 1);
            nchn = (cn + 15) >> 4;
            if (lane < nchn)
                vn = ((const uint4*)(g_lst + (size_t)(cb + i + 1) * 256))[lane];
        }
        const int cnt = __shfl_sync(0xffffffffu, mycnt, i);
        const unsigned* lb = mybuf + (i & 1) * 64;

        float2 acc = bias2;
        int k = 0;
        for (; k + 4 <= cnt; k += 4) {
            unsigned w = lb[k >> 2];
            int j0 = w & 255, j1 = (w >> 8) & 255, j2 = (w >> 16) & 255, j3 = w >> 24;
            float2 v0 = w2[j0 * 32 + lane];
            float2 v1 = w2[j1 * 32 + lane];
            float2 v2 = w2[j2 * 32 + lane];
            float2 v3 = w2[j3 * 32 + lane];
            acc.x += v0.x; acc.y += v0.y;
            acc.x += v1.x; acc.y += v1.y;
            acc.x += v2.x; acc.y += v2.y;
            acc.x += v3.x; acc.y += v3.y;
        }
        if (k < cnt) {
            unsigned w = lb[k >> 2];
            for (; k < cnt; k++) {
                int j = (w >> (8 * (k & 3))) & 255;
                float2 v = w2[j * 32 + lane];
                acc.x += v.x; acc.y += v.y;
            }
        }

        ((float2*)(g_i1 + (size_t)t * BN + (size_t)(bbase + i) * NN + q * 64))[lane] = acc;

        if (i + 1 < 32 && lane < nchn) {
            unsigned* d = mybuf + ((i + 1) & 1) * 64 + lane * 4;
            d[0] = vn.x; d[1] = vn.y; d[2] = vn.z; d[3] = vn.w;
        }
        __syncwarp();
    }
}

// ------------------------- K3: recurrent chunk (R10 core + state spill) -----
__global__ void __launch_bounds__(256)
k3_recurrent(const float* __restrict__ W3, const float* __restrict__ b3,
             const float* __restrict__ tau_adp2, const float* __restrict__ tau_m2,
             const float* __restrict__ tau_m3, int t0, int t1)
{
    __shared__ float    W3s[OUTN * 257];
    __shared__ unsigned words[8];
    __shared__ int      lst2[256];

    const int b    = blockIdx.x;
    const int tid  = threadIdx.x;
    const int n    = tid;
    const int lane = tid & 31;
    const int wid  = tid >> 5;
    const unsigned ltm = (1u << lane) - 1u;
    const int gid  = b * NN + n;
    const bool first = (t0 == 0), last = (t1 == TT);

    for (int i = tid; i < OUTN * NN; i += 256)
        W3s[(i >> 8) * 257 + (i & 255)] = W3[i];
    if (tid < 8) words[tid] = first ? 0u : g_k3w[b * 8 + tid];

    const float al = __expf(-1.0f / tau_m2[n]);
    const float rh = __expf(-1.0f / tau_adp2[n]);
    float m2, a2, s2;
    if (first) { m2 = 0.f; a2 = B_J0; s2 = 0.f; }
    else { m2 = g_k3m2[gid]; a2 = g_k3a2[gid]; s2 = g_k3s2[gid]; }

    float al3 = 1.f, m3 = 0.f, accr = 0.f, b3v = 0.f;
    if (tid < OUTN) {
        al3 = __expf(-1.0f / tau_m3[tid]);
        b3v = b3[tid];
        if (!first) { m3 = g_k3m3[b * OUTN + tid]; accr = g_k3ac[b * OUTN + tid]; }
    }

    const float* __restrict__ w2rf = g_W2recTp;
    const float* __restrict__ i2p  = g_i1 + gid;

    __syncthreads();

    float iv = i2p[(size_t)t0 * BN];

    for (int t = t0; t < t1; t++) {
        __syncthreads();   // prev ballots visible; lst2 free

        const int tn = (t + 1 < t1) ? (t + 1) : t;
        float nv = i2p[(size_t)tn * BN];

        if (tid < OUTN && t > 0) {
            float i3 = b3v;
            const float* wr = &W3s[tid * 257];
            #pragma unroll
            for (int w = 0; w < 8; w++) {
                unsigned mm = words[w];
                int base = w * 32;
                while (mm) {
                    int j = __ffs((int)mm) - 1;
                    mm &= mm - 1;
                    i3 += wr[base + j];
                }
            }
            m3 = al3 * m3 + (1.0f - al3) * i3;
            accr += m3;
        }

        unsigned wv[8];
        #pragma unroll
        for (int w = 0; w < 8; w++) wv[w] = words[w];
        int off = 0, myoff = 0;
        #pragma unroll
        for (int w = 0; w < 8; w++) {
            if (w == wid) myoff = off;
            off += __popc(wv[w]);
        }
        const int cnt2 = off;
        unsigned wd = wv[wid];
        if ((wd >> lane) & 1u)
            lst2[myoff + __popc(wd & ltm)] = wid * 32 + lane;
        __syncthreads();

        float i2 = iv;
        {
            int k = 0;
            for (; k + 8 <= cnt2; k += 8) {
                int j0 = lst2[k],     j1 = lst2[k + 1], j2 = lst2[k + 2], j3 = lst2[k + 3];
                int j4 = lst2[k + 4], j5 = lst2[k + 5], j6 = lst2[k + 6], j7 = lst2[k + 7];
                float v0 = w2rf[j0 * NN + n];
                float v1 = w2rf[j1 * NN + n];
                float v2 = w2rf[j2 * NN + n];
                float v3 = w2rf[j3 * NN + n];
                float v4 = w2rf[j4 * NN + n];
                float v5 = w2rf[j5 * NN + n];
                float v6 = w2rf[j6 * NN + n];
                float v7 = w2rf[j7 * NN + n];
                i2 += v0; i2 += v1; i2 += v2; i2 += v3;
                i2 += v4; i2 += v5; i2 += v6; i2 += v7;
            }
            for (; k < cnt2; k++) i2 += w2rf[lst2[k] * NN + n];
        }

        a2 = rh * a2 + (1.0f - rh) * s2;
        float Bth = B_J0 + BETA * a2;
        m2 = al * m2 + (1.0f - al) * i2 - Bth * s2;
        s2 = (m2 - Bth > 0.f) ? 1.f : 0.f;

        unsigned bal = __ballot_sync(0xffffffffu, s2 > 0.5f);
        if (lane == 0) words[wid] = bal;
        iv = nv;
    }

    __syncthreads();
    if (last) {
        if (tid < OUTN) {
            float i3 = b3v;
            const float* wr = &W3s[tid * 257];
            #pragma unroll
            for (int w = 0; w < 8; w++) {
                unsigned mm = words[w];
                int base = w * 32;
                while (mm) {
                    int j = __ffs((int)mm) - 1;
                    mm &= mm - 1;
                    i3 += wr[base + j];
                }
            }
            m3 = al3 * m3 + (1.0f - al3) * i3;
            accr += m3;
            g_acc[b * OUTN + tid] = accr;
        }
    } else {
        g_k3m2[gid] = m2; g_k3a2[gid] = a2; g_k3s2[gid] = s2;
        if (tid < 8) g_k3w[b * 8 + tid] = words[tid];
        if (tid < OUTN) { g_k3m3[b * OUTN + tid] = m3; g_k3ac[b * OUTN + tid] = accr; }
    }
}

// ------------------------- K4: log-softmax ----------------------------------
__global__ void __launch_bounds__(256)
k4_softmax(float* __restrict__ out)
{
    int b = blockIdx.x * 256 + threadIdx.x;
    if (b >= BB) return;
    float v[OUTN];
    float mx = -1e30f;
    #pragma unroll
    for (int o = 0; o < OUTN; o++) {
        v[o] = g_acc[b * OUTN + o] * (1.0f / (float)TT);
        mx = fmaxf(mx, v[o]);
    }
    float sum = 0.f;
    #pragma unroll
    for (int o = 0; o < OUTN; o++) sum += __expf(v[o] - mx);
    float lse = mx + __logf(sum);
    #pragma unroll
    for (int o = 0; o < OUTN; o++) out[b * OUTN + o] = v[o] - lse;
}

// ------------------------- launch: priority-pipelined uneven chunks ---------
// Small first chunk starts K3 early; 4 chunks total keep spill overhead at
// the R13 level.
static const int CH[NCH + 1] = {0, 48, 176, 336, 500};

extern "C" void kernel_launch(void* const* d_in, const int* in_sizes, int n_in,
                              void* d_out, int out_size)
{
    const float* x        = (const float*)d_in[0];
    const float* thr      = (const float*)d_in[1];
    const float* W1       = (const float*)d_in[2];
    const float* b1       = (const float*)d_in[3];
    const float* W2_in    = (const float*)d_in[4];
    const float* b2_in    = (const float*)d_in[5];
    const float* W2_rec   = (const float*)d_in[6];
    const float* b2_rec   = (const float*)d_in[7];
    const float* W3       = (const float*)d_in[8];
    const float* b3       = (const float*)d_in[9];
    const float* tau_adp1 = (const float*)d_in[10];
    const float* tau_m1   = (const float*)d_in[11];
    const float* tau_adp2 = (const float*)d_in[12];
    const float* tau_m2   = (const float*)d_in[13];
    const float* tau_m3   = (const float*)d_in[14];
    float* out = (float*)d_out;

    static cudaStream_t sB = nullptr;
    static cudaEvent_t  evFork, evP[NCH], evJoin;
    if (sB == nullptr) {
        int loPri = 0, hiPri = 0;
        cudaDeviceGetStreamPriorityRange(&loPri, &hiPri);
        cudaStreamCreateWithPriority(&sB, cudaStreamNonBlocking, hiPri);
        cudaEventCreateWithFlags(&evFork, cudaEventDisableTiming);
        for (int c = 0; c < NCH; c++)
            cudaEventCreateWithFlags(&evP[c], cudaEventDisableTiming);
        cudaEventCreateWithFlags(&evJoin, cudaEventDisableTiming);
    }

    cudaFuncSetAttribute(k1_gemm1,    cudaFuncAttributeMaxDynamicSharedMemorySize, K1_SMEM);
    cudaFuncSetAttribute(k25_gemm2in, cudaFuncAttributeMaxDynamicSharedMemorySize, K25_SMEM);

    // prologue pipeline on the capture stream (default priority)
    k0_prep<<<NN, NN>>>(W2_in, W2_rec, W1);
    cudaEventRecord(evFork, 0);
    cudaStreamWaitEvent(sB, evFork, 0);

    for (int c = 0; c < NCH; c++) {
        const int t0 = CH[c], t1 = CH[c + 1], len = t1 - t0;
        k1_gemm1<<<len * 8, 512, K1_SMEM>>>(x, thr, b1, t0);
        k2_scan1<<<BB, 256>>>(tau_adp1, tau_m1, t0, t1);
        k25_gemm2in<<<len * 8, 256, K25_SMEM>>>(b2_in, b2_rec, t0);
        cudaEventRecord(evP[c], 0);
    }

    // recurrent core on the high-priority stream, gated per chunk
    for (int c = 0; c < NCH; c++) {
        cudaStreamWaitEvent(sB, evP[c], 0);
        k3_recurrent<<<BB, 256, 0, sB>>>(W3, b3, tau_adp2, tau_m2, tau_m3,
                                         CH[c], CH[c + 1]);
    }
    cudaEventRecord(evJoin, sB);
    cudaStreamWaitEvent(0, evJoin, 0);

    k4_softmax<<<(BB + 255) / 256, 256>>>(out);
}

// round 17
// speedup vs baseline: 1.0623x; 1.0258x over previous
#include <cuda_runtime.h>
#include <cuda_bf16.h>
#include <cstdint>

#define BB   512
#define CC   3
#define TT   500
#define DD   40
#define CD   120
#define NN   256
#define OUTN 12
#define BN   (BB*NN)        // 131072
#define B_J0 0.01f
#define BETA 1.8f
#define NCH  4

// ------------------------- device scratch (allocation-guard-safe) -----------
__device__ float         g_i1[(size_t)TT * BB * NN];   // 262 MB (i1, then i2in)
__device__ unsigned char g_lst[(size_t)TT * BB * 256]; // 65.5 MB s1 index lists
__device__ int           g_cnt[TT * BB];               // list lengths
__device__ float         g_W2inQ[4 * 256 * 64];        // [q][j][nl] quarters
__device__ float         g_W2recTp[NN * NN];           // [j][n]
__device__ __nv_bfloat16 g_W1hi[256 * 136];            // padded [n][136] bf16 hi
__device__ __nv_bfloat16 g_W1lo[256 * 136];            // padded [n][136] bf16 lo
__device__ float         g_acc[BB * OUTN];
// chunk-boundary state
__device__ float         g_k2m[BN], g_k2a[BN], g_k2s[BN];
__device__ float         g_k3m2[BN], g_k3a2[BN], g_k3s2[BN];
__device__ unsigned      g_k3w[BB * 8];
__device__ float         g_k3m3[BB * OUTN], g_k3ac[BB * OUTN];

// ------------------------- helpers ------------------------------------------
__device__ __forceinline__ unsigned smem_u32(const void* p) {
    return (unsigned)__cvta_generic_to_shared(p);
}
__device__ __forceinline__ void ldsm_x4(uint32_t& r0, uint32_t& r1,
                                        uint32_t& r2, uint32_t& r3, unsigned addr) {
    asm volatile("ldmatrix.sync.aligned.m8n8.x4.shared.b16 {%0,%1,%2,%3}, [%4];"
                 : "=r"(r0), "=r"(r1), "=r"(r2), "=r"(r3) : "r"(addr));
}
__device__ __forceinline__ void ldsm_x2(uint32_t& r0, uint32_t& r1, unsigned addr) {
    asm volatile("ldmatrix.sync.aligned.m8n8.x2.shared.b16 {%0,%1}, [%2];"
                 : "=r"(r0), "=r"(r1) : "r"(addr));
}
__device__ __forceinline__ void mma16816(float& c0, float& c1, float& c2, float& c3,
                                         uint32_t a0, uint32_t a1, uint32_t a2, uint32_t a3,
                                         uint32_t b0, uint32_t b1) {
    asm volatile("mma.sync.aligned.m16n8k16.row.col.f32.bf16.bf16.f32 "
                 "{%0,%1,%2,%3}, {%4,%5,%6,%7}, {%8,%9}, {%0,%1,%2,%3};"
                 : "+f"(c0), "+f"(c1), "+f"(c2), "+f"(c3)
                 : "r"(a0), "r"(a1), "r"(a2), "r"(a3), "r"(b0), "r"(b1));
}

// ------------------------- K0: weight layout prep ---------------------------
__global__ void k0_prep(const float* __restrict__ W2_in,
                        const float* __restrict__ W2_rec,
                        const float* __restrict__ W1)
{
    int j = blockIdx.x;
    int n = threadIdx.x;
    g_W2recTp[j * NN + n] = W2_rec[n * NN + j];
    g_W2inQ[(((n >> 6) * 256) + j) * 64 + (n & 63)] = W2_in[n * NN + j];
    if (n < 136) {
        float f = (n < CD) ? W1[j * CD + n] : 0.0f;
        __nv_bfloat16 hb = __float2bfloat16(f);
        __nv_bfloat16 lb = __float2bfloat16(f - __bfloat162float(hb));
        g_W1hi[j * 136 + n] = hb;
        g_W1lo[j * 136 + n] = lb;
    }
}

// ------------------------- K1: spikify + i1 GEMM via tensor cores -----------
// Streaming cache policy on use-once x reads and i1 writes keeps L1/L2 clean
// for the reused weight lines.
#define K1_LDK 136
#define K1_SMEM (64*K1_LDK*2 + 2*256*K1_LDK*2)   // 156672
__global__ void __launch_bounds__(512, 1)
k1_gemm1(const float* __restrict__ x, const float* __restrict__ thrp,
         const float* __restrict__ b1, int t0)
{
    extern __shared__ char smraw[];
    __nv_bfloat16* xs  = (__nv_bfloat16*)smraw;                        // [64][136]
    __nv_bfloat16* whi = (__nv_bfloat16*)(smraw + 64*K1_LDK*2);        // [256][136]
    __nv_bfloat16* wlo = (__nv_bfloat16*)(smraw + 64*K1_LDK*2 + 256*K1_LDK*2);

    const int tid = threadIdx.x;
    const int p0  = blockIdx.x * 64 + t0 * BB;
    const int t   = p0 >> 9;
    const int b0  = p0 & 511;
    const float thr = *thrp;

    for (int i = tid; i < 4352; i += 512) {
        ((float4*)whi)[i] = ((const float4*)g_W1hi)[i];
        ((float4*)wlo)[i] = ((const float4*)g_W1lo)[i];
    }
    {
        const __nv_bfloat16 z = __float2bfloat16(0.0f);
        for (int i = tid; i < 64 * 8; i += 512) {
            int r = i >> 3, k = 120 + (i & 7);
            xs[r * K1_LDK + k] = z;
        }
    }
    for (int i = tid; i < 64 * CD; i += 512) {
        int r  = i / CD;
        int cd = i % CD;
        int c  = cd / DD, d = cd % DD;
        float xv = __ldcs(&x[(((size_t)(b0 + r) * CC + c) * TT + t) * DD + d]);
        float s  = (xv > thr) ? 1.0f : ((xv < -thr) ? -1.0f : 0.0f);
        xs[r * K1_LDK + cd] = __float2bfloat16(s);
    }
    __syncthreads();

    const int warp = tid >> 5, lane = tid & 31;
    const int mb = (warp & 3) * 16;
    const int nb = (warp >> 2) * 64;

    float acc[8][4];
    #pragma unroll
    for (int j = 0; j < 8; j++)
        #pragma unroll
        for (int u = 0; u < 4; u++) acc[j][u] = 0.0f;

    const unsigned a_base  = smem_u32(xs)  + (unsigned)(mb + (lane & 15)) * (K1_LDK * 2)
                                           + ((lane >> 4) << 4);
    const unsigned bkoff   = ((lane >> 3) & 1) << 4;
    const unsigned bh_base = smem_u32(whi) + (unsigned)(nb + (lane & 7)) * (K1_LDK * 2) + bkoff;
    const unsigned bl_base = smem_u32(wlo) + (unsigned)(nb + (lane & 7)) * (K1_LDK * 2) + bkoff;

    #pragma unroll
    for (int kt = 0; kt < 8; kt++) {
        uint32_t a0, a1, a2, a3;
        ldsm_x4(a0, a1, a2, a3, a_base + kt * 32);
        #pragma unroll
        for (int j = 0; j < 8; j++) {
            uint32_t br0, br1;
            ldsm_x2(br0, br1, bh_base + (unsigned)j * (8 * K1_LDK * 2) + kt * 32);
            mma16816(acc[j][0], acc[j][1], acc[j][2], acc[j][3],
                     a0, a1, a2, a3, br0, br1);
            ldsm_x2(br0, br1, bl_base + (unsigned)j * (8 * K1_LDK * 2) + kt * 32);
            mma16816(acc[j][0], acc[j][1], acc[j][2], acc[j][3],
                     a0, a1, a2, a3, br0, br1);
        }
    }

    const int g  = lane >> 2, tg = lane & 3;
    const int r0 = mb + g, r1 = r0 + 8;
    #pragma unroll
    for (int j = 0; j < 8; j++) {
        int n = nb + j * 8 + tg * 2;
        float2 bv = *(const float2*)&b1[n];
        size_t base0 = (size_t)t * BN + (size_t)(b0 + r0) * NN + n;
        size_t base1 = (size_t)t * BN + (size_t)(b0 + r1) * NN + n;
        __stcs((float2*)&g_i1[base0], make_float2(acc[j][0] + bv.x, acc[j][1] + bv.y));
        __stcs((float2*)&g_i1[base1], make_float2(acc[j][2] + bv.x, acc[j][3] + bv.y));
    }
}

// ------------------------- K2: layer-1 ALIF scan chunk ----------------------
__global__ void __launch_bounds__(256)
k2_scan1(const float* __restrict__ tau_adp1, const float* __restrict__ tau_m1,
         int t0, int t1)
{
    __shared__ unsigned swords[2][4][8];

    const int b    = blockIdx.x;
    const int tid  = threadIdx.x;
    const int n    = tid;
    const int lane = tid & 31;
    const int wid  = tid >> 5;
    const unsigned ltm = (1u << lane) - 1u;
    const int gid  = b * NN + n;

    const float alpha = __expf(-1.0f / tau_m1[n]);
    const float rho   = __expf(-1.0f / tau_adp1[n]);
    const float ca = 1.0f - alpha, cr = 1.0f - rho;

    float m, a, s;
    if (t0 == 0) { m = 0.f; a = B_J0; s = 0.f; }
    else { m = g_k2m[gid]; a = g_k2a[gid]; s = g_k2s[gid]; }

    const float* ip = g_i1 + gid;

    for (int t4 = t0; t4 < t1; t4 += 4) {
        const int buf = (t4 >> 2) & 1;
        float iv[4];
        #pragma unroll
        for (int k = 0; k < 4; k++) iv[k] = __ldcs(ip + (size_t)(t4 + k) * BN);
        #pragma unroll
        for (int k = 0; k < 4; k++) {
            a = rho * a + cr * s;
            float Bth = B_J0 + BETA * a;
            m = alpha * m + ca * iv[k] - Bth * s;
            s = (m - Bth > 0.f) ? 1.f : 0.f;
            unsigned bal = __ballot_sync(0xffffffffu, s > 0.5f);
            if (lane == 0) swords[buf][k][wid] = bal;
        }
        __syncthreads();
        #pragma unroll
        for (int k = 0; k < 4; k++) {
            const int t = t4 + k;
            unsigned wv[8];
            #pragma unroll
            for (int w = 0; w < 8; w++) wv[w] = swords[buf][k][w];
            int off = 0, myoff = 0;
            #pragma unroll
            for (int w = 0; w < 8; w++) {
                if (w == wid) myoff = off;
                off += __popc(wv[w]);
            }
            unsigned wd = wv[wid];
            if ((wd >> lane) & 1u)
                g_lst[(size_t)(t * BB + b) * 256 + myoff + __popc(wd & ltm)] =
                    (unsigned char)(wid * 32 + lane);
            if (tid == 0) g_cnt[t * BB + b] = off;
        }
    }
    if (t1 != TT) { g_k2m[gid] = m; g_k2a[gid] = a; g_k2s[gid] = s; }
}

// ------------------------- K2.5: i2in chunk (R5 core + streaming stores) ----
#define K25_SMEM (64*1024 + 8*2*64*4)
__global__ void __launch_bounds__(256, 2)
k25_gemm2in(const float* __restrict__ b2_in, const float* __restrict__ b2_rec,
            int t0)
{
    extern __shared__ float sm[];
    float2*   w2  = (float2*)sm;                  // [j*32+lane] pairs
    unsigned* lsb = (unsigned*)(sm + 16384);      // [8 warps][2][64]

    const int idx  = blockIdx.x;
    const int q    = idx & 3;
    const int bh   = (idx >> 2) & 1;
    const int t    = (idx >> 3) + t0;
    const int tid  = threadIdx.x;
    const int lane = tid & 31;
    const int wid  = tid >> 5;

    {
        const float4* src = (const float4*)(g_W2inQ + q * 256 * 64);
        float4* dst = (float4*)sm;
        for (int i = tid; i < 4096; i += 256) dst[i] = src[i];
    }
    const int n0 = q * 64 + lane * 2;
    const float2 bias2 = make_float2(b2_in[n0] + b2_rec[n0],
                                     b2_in[n0 + 1] + b2_rec[n0 + 1]);
    __syncthreads();

    const int bbase = bh * 256 + wid * 32;
    const int cb    = t * BB + bbase;
    const int mycnt = g_cnt[cb + lane];
    unsigned* mybuf = lsb + wid * 128;

    {
        int c0  = __shfl_sync(0xffffffffu, mycnt, 0);
        int nch = (c0 + 15) >> 4;
        if (lane < nch) {
            uint4 v = __ldcs((const uint4*)(g_lst + (size_t)cb * 256) + lane);
            unsigned* d = mybuf + lane * 4;
            d[0] = v.x; d[1] = v.y; d[2] = v.z; d[3] = v.w;
        }
        __syncwarp();
    }

    for (int i = 0; i < 32; i++) {
        uint4 vn = make_uint4(0, 0, 0, 0);
        int nchn = 0;
        if (i + 1 < 32) {
            int cn = __shfl_sync(0xffffffffu, mycnt, i + 1);
            nchn = (cn + 15) >> 4;
            if (lane < nchn)
                vn = __ldcs((const uint4*)(g_lst + (size_t)(cb + i + 1) * 256) + lane);
        }
        const int cnt = __shfl_sync(0xffffffffu, mycnt, i);
        const unsigned* lb = mybuf + (i & 1) * 64;

        float2 acc = bias2;
        int k = 0;
        for (; k + 4 <= cnt; k += 4) {
            unsigned w = lb[k >> 2];
            int j0 = w & 255, j1 = (w >> 8) & 255, j2 = (w >> 16) & 255, j3 = w >> 24;
            float2 v0 = w2[j0 * 32 + lane];
            float2 v1 = w2[j1 * 32 + lane];
            float2 v2 = w2[j2 * 32 + lane];
            float2 v3 = w2[j3 * 32 + lane];
            acc.x += v0.x; acc.y += v0.y;
            acc.x += v1.x; acc.y += v1.y;
            acc.x += v2.x; acc.y += v2.y;
            acc.x += v3.x; acc.y += v3.y;
        }
        if (k < cnt) {
            unsigned w = lb[k >> 2];
            for (; k < cnt; k++) {
                int j = (w >> (8 * (k & 3))) & 255;
                float2 v = w2[j * 32 + lane];
                acc.x += v.x; acc.y += v.y;
            }
        }

        __stcs((float2*)(g_i1 + (size_t)t * BN + (size_t)(bbase + i) * NN + q * 64) + lane,
               acc);

        if (i + 1 < 32 && lane < nchn) {
            unsigned* d = mybuf + ((i + 1) & 1) * 64 + lane * 4;
            d[0] = vn.x; d[1] = vn.y; d[2] = vn.z; d[3] = vn.w;
        }
        __syncwarp();
    }
}

// ------------------------- K3: recurrent chunk (R10 core + streaming i2in) --
__global__ void __launch_bounds__(256)
k3_recurrent(const float* __restrict__ W3, const float* __restrict__ b3,
             const float* __restrict__ tau_adp2, const float* __restrict__ tau_m2,
             const float* __restrict__ tau_m3, int t0, int t1)
{
    __shared__ float    W3s[OUTN * 257];
    __shared__ unsigned words[8];
    __shared__ int      lst2[256];

    const int b    = blockIdx.x;
    const int tid  = threadIdx.x;
    const int n    = tid;
    const int lane = tid & 31;
    const int wid  = tid >> 5;
    const unsigned ltm = (1u << lane) - 1u;
    const int gid  = b * NN + n;
    const bool first = (t0 == 0), last = (t1 == TT);

    for (int i = tid; i < OUTN * NN; i += 256)
        W3s[(i >> 8) * 257 + (i & 255)] = W3[i];
    if (tid < 8) words[tid] = first ? 0u : g_k3w[b * 8 + tid];

    const float al = __expf(-1.0f / tau_m2[n]);
    const float rh = __expf(-1.0f / tau_adp2[n]);
    float m2, a2, s2;
    if (first) { m2 = 0.f; a2 = B_J0; s2 = 0.f; }
    else { m2 = g_k3m2[gid]; a2 = g_k3a2[gid]; s2 = g_k3s2[gid]; }

    float al3 = 1.f, m3 = 0.f, accr = 0.f, b3v = 0.f;
    if (tid < OUTN) {
        al3 = __expf(-1.0f / tau_m3[tid]);
        b3v = b3[tid];
        if (!first) { m3 = g_k3m3[b * OUTN + tid]; accr = g_k3ac[b * OUTN + tid]; }
    }

    const float* __restrict__ w2rf = g_W2recTp;
    const float* __restrict__ i2p  = g_i1 + gid;

    __syncthreads();

    float iv = __ldcs(i2p + (size_t)t0 * BN);

    for (int t = t0; t < t1; t++) {
        __syncthreads();   // prev ballots visible; lst2 free

        const int tn = (t + 1 < t1) ? (t + 1) : t;
        float nv = __ldcs(i2p + (size_t)tn * BN);

        if (tid < OUTN && t > 0) {
            float i3 = b3v;
            const float* wr = &W3s[tid * 257];
            #pragma unroll
            for (int w = 0; w < 8; w++) {
                unsigned mm = words[w];
                int base = w * 32;
                while (mm) {
                    int j = __ffs((int)mm) - 1;
                    mm &= mm - 1;
                    i3 += wr[base + j];
                }
            }
            m3 = al3 * m3 + (1.0f - al3) * i3;
            accr += m3;
        }

        unsigned wv[8];
        #pragma unroll
        for (int w = 0; w < 8; w++) wv[w] = words[w];
        int off = 0, myoff = 0;
        #pragma unroll
        for (int w = 0; w < 8; w++) {
            if (w == wid) myoff = off;
            off += __popc(wv[w]);
        }
        const int cnt2 = off;
        unsigned wd = wv[wid];
        if ((wd >> lane) & 1u)
            lst2[myoff + __popc(wd & ltm)] = wid * 32 + lane;
        __syncthreads();

        float i2 = iv;
        {
            int k = 0;
            for (; k + 8 <= cnt2; k += 8) {
                int j0 = lst2[k],     j1 = lst2[k + 1], j2 = lst2[k + 2], j3 = lst2[k + 3];
                int j4 = lst2[k + 4], j5 = lst2[k + 5], j6 = lst2[k + 6], j7 = lst2[k + 7];
                float v0 = w2rf[j0 * NN + n];
                float v1 = w2rf[j1 * NN + n];
                float v2 = w2rf[j2 * NN + n];
                float v3 = w2rf[j3 * NN + n];
                float v4 = w2rf[j4 * NN + n];
                float v5 = w2rf[j5 * NN + n];
                float v6 = w2rf[j6 * NN + n];
                float v7 = w2rf[j7 * NN + n];
                i2 += v0; i2 += v1; i2 += v2; i2 += v3;
                i2 += v4; i2 += v5; i2 += v6; i2 += v7;
            }
            for (; k < cnt2; k++) i2 += w2rf[lst2[k] * NN + n];
        }

        a2 = rh * a2 + (1.0f - rh) * s2;
        float Bth = B_J0 + BETA * a2;
        m2 = al * m2 + (1.0f - al) * i2 - Bth * s2;
        s2 = (m2 - Bth > 0.f) ? 1.f : 0.f;

        unsigned bal = __ballot_sync(0xffffffffu, s2 > 0.5f);
        if (lane == 0) words[wid] = bal;
        iv = nv;
    }

    __syncthreads();
    if (last) {
        if (tid < OUTN) {
            float i3 = b3v;
            const float* wr = &W3s[tid * 257];
            #pragma unroll
            for (int w = 0; w < 8; w++) {
                unsigned mm = words[w];
                int base = w * 32;
                while (mm) {
                    int j = __ffs((int)mm) - 1;
                    mm &= mm - 1;
                    i3 += wr[base + j];
                }
            }
            m3 = al3 * m3 + (1.0f - al3) * i3;
            accr += m3;
            g_acc[b * OUTN + tid] = accr;
        }
    } else {
        g_k3m2[gid] = m2; g_k3a2[gid] = a2; g_k3s2[gid] = s2;
        if (tid < 8) g_k3w[b * 8 + tid] = words[tid];
        if (tid < OUTN) { g_k3m3[b * OUTN + tid] = m3; g_k3ac[b * OUTN + tid] = accr; }
    }
}

// ------------------------- K4: log-softmax ----------------------------------
__global__ void __launch_bounds__(256)
k4_softmax(float* __restrict__ out)
{
    int b = blockIdx.x * 256 + threadIdx.x;
    if (b >= BB) return;
    float v[OUTN];
    float mx = -1e30f;
    #pragma unroll
    for (int o = 0; o < OUTN; o++) {
        v[o] = g_acc[b * OUTN + o] * (1.0f / (float)TT);
        mx = fmaxf(mx, v[o]);
    }
    float sum = 0.f;
    #pragma unroll
    for (int o = 0; o < OUTN; o++) sum += __expf(v[o] - mx);
    float lse = mx + __logf(sum);
    #pragma unroll
    for (int o = 0; o < OUTN; o++) out[b * OUTN + o] = v[o] - lse;
}

// ------------------------- launch: priority-pipelined chunks (R13 layout) ---
static const int CH[NCH + 1] = {0, 128, 256, 384, 500};

extern "C" void kernel_launch(void* const* d_in, const int* in_sizes, int n_in,
                              void* d_out, int out_size)
{
    const float* x        = (const float*)d_in[0];
    const float* thr      = (const float*)d_in[1];
    const float* W1       = (const float*)d_in[2];
    const float* b1       = (const float*)d_in[3];
    const float* W2_in    = (const float*)d_in[4];
    const float* b2_in    = (const float*)d_in[5];
    const float* W2_rec   = (const float*)d_in[6];
    const float* b2_rec   = (const float*)d_in[7];
    const float* W3       = (const float*)d_in[8];
    const float* b3       = (const float*)d_in[9];
    const float* tau_adp1 = (const float*)d_in[10];
    const float* tau_m1   = (const float*)d_in[11];
    const float* tau_adp2 = (const float*)d_in[12];
    const float* tau_m2   = (const float*)d_in[13];
    const float* tau_m3   = (const float*)d_in[14];
    float* out = (float*)d_out;

    static cudaStream_t sB = nullptr;
    static cudaEvent_t  evFork, evP[NCH], evJoin;
    if (sB == nullptr) {
        int loPri = 0, hiPri = 0;
        cudaDeviceGetStreamPriorityRange(&loPri, &hiPri);
        cudaStreamCreateWithPriority(&sB, cudaStreamNonBlocking, hiPri);
        cudaEventCreateWithFlags(&evFork, cudaEventDisableTiming);
        for (int c = 0; c < NCH; c++)
            cudaEventCreateWithFlags(&evP[c], cudaEventDisableTiming);
        cudaEventCreateWithFlags(&evJoin, cudaEventDisableTiming);
    }

    cudaFuncSetAttribute(k1_gemm1,    cudaFuncAttributeMaxDynamicSharedMemorySize, K1_SMEM);
    cudaFuncSetAttribute(k25_gemm2in, cudaFuncAttributeMaxDynamicSharedMemorySize, K25_SMEM);

    // prologue pipeline on the capture stream (default priority)
    k0_prep<<<NN, NN>>>(W2_in, W2_rec, W1);
    cudaEventRecord(evFork, 0);
    cudaStreamWaitEvent(sB, evFork, 0);

    for (int c = 0; c < NCH; c++) {
        const int t0 = CH[c], t1 = CH[c + 1], len = t1 - t0;
        k1_gemm1<<<len * 8, 512, K1_SMEM>>>(x, thr, b1, t0);
        k2_scan1<<<BB, 256>>>(tau_adp1, tau_m1, t0, t1);
        k25_gemm2in<<<len * 8, 256, K25_SMEM>>>(b2_in, b2_rec, t0);
        cudaEventRecord(evP[c], 0);
    }

    // recurrent core on the high-priority stream, gated per chunk
    for (int c = 0; c < NCH; c++) {
        cudaStreamWaitEvent(sB, evP[c], 0);
        k3_recurrent<<<BB, 256, 0, sB>>>(W3, b3, tau_adp2, tau_m2, tau_m3,
                                         CH[c], CH[c + 1]);
    }
    cudaEventRecord(evJoin, sB);
    cudaStreamWaitEvent(0, evJoin, 0);

    k4_softmax<<<(BB + 255) / 256, 256>>>(out);
}